// round 1
// baseline (speedup 1.0000x reference)
#include <cuda_runtime.h>
#include <math.h>

// Problem dims
constexpr int kB = 512;   // batch
constexpr int kS = 168;   // encoder seq len
constexpr int kI = 8;     // input features
constexpr int kH = 512;   // hidden
constexpr int kF = 256;   // fc1 width
constexpr int kP = 24;    // decoder steps
constexpr int kG = 4 * kH; // 2048 gates

// ---------------- scratch (device globals; no allocations allowed) ----------
__device__ float g_y0[(size_t)kS * kB * 2 * kH];   // BiLSTM L0 output concat [s][b][1024]
__device__ float g_G1[(size_t)2 * kS * kB * kG];   // precomputed L1 input projections [d][s][b][2048]
__device__ float g_h[8][kB * kH];                  // 4 encoder runs x ping-pong
__device__ float g_c[4][kB * kH];                  // 4 encoder runs (in-place)
__device__ float g_dh[4][kB * kH];                 // decoder: 2 cells x ping-pong
__device__ float g_dc[2][kB * kH];
__device__ float g_din[kB * kI];                   // decoder input vector
__device__ float g_z[kB * kF];                     // fc1 activations

// ---------------- shared tile layout ----------------------------------------
struct SmemT {
    float As[16][64];     // A tile: As[k][row]
    float Bs[128][17];    // B tile: Bs[j_local][k], padded stride 17 (conflict-free)
};

// Tiled GEMM accumulate: block computes 64 rows x 128 weight-rows, K loop.
// Weight-row mapping: j_global = (j_local/32)*gstride + ubase + (j_local%32).
// For LSTM gates: gstride=512 -> thread (u = tid&31) owns gates i,f,g,o of unit ubase+u.
// For plain GEMM: gstride=32 -> j_global = ubase + j_local (contiguous 128 cols).
__device__ __forceinline__ void gemm_acc(
    float acc[4][8],
    const float* __restrict__ A, int lda,
    const float* __restrict__ Bm, int ldb,
    int K, int gstride, int ubase,
    SmemT& sm)
{
    const int tid = threadIdx.x;
    const int u = tid & 31, rg = tid >> 5;
    const int lrow = tid >> 2;
    const int lk4 = (tid & 3) * 4;
    for (int k0 = 0; k0 < K; k0 += 16) {
        __syncthreads();
        {
            float4 v = *reinterpret_cast<const float4*>(A + (size_t)lrow * lda + k0 + lk4);
            sm.As[lk4 + 0][lrow] = v.x;
            sm.As[lk4 + 1][lrow] = v.y;
            sm.As[lk4 + 2][lrow] = v.z;
            sm.As[lk4 + 3][lrow] = v.w;
        }
#pragma unroll
        for (int pass = 0; pass < 2; ++pass) {
            int jl = lrow + pass * 64;
            int jg = (jl >> 5) * gstride + ubase + (jl & 31);
            float4 v = *reinterpret_cast<const float4*>(Bm + (size_t)jg * ldb + k0 + lk4);
            sm.Bs[jl][lk4 + 0] = v.x;
            sm.Bs[jl][lk4 + 1] = v.y;
            sm.Bs[jl][lk4 + 2] = v.z;
            sm.Bs[jl][lk4 + 3] = v.w;
        }
        __syncthreads();
#pragma unroll
        for (int kk = 0; kk < 16; ++kk) {
            float4 a0 = *reinterpret_cast<const float4*>(&sm.As[kk][rg * 8]);
            float4 a1 = *reinterpret_cast<const float4*>(&sm.As[kk][rg * 8 + 4]);
            float b0 = sm.Bs[u][kk];
            float b1 = sm.Bs[32 + u][kk];
            float b2 = sm.Bs[64 + u][kk];
            float b3 = sm.Bs[96 + u][kk];
            float a[8] = {a0.x, a0.y, a0.z, a0.w, a1.x, a1.y, a1.z, a1.w};
#pragma unroll
            for (int i = 0; i < 8; ++i) {
                acc[0][i] += b0 * a[i];
                acc[1][i] += b1 * a[i];
                acc[2][i] += b2 * a[i];
                acc[3][i] += b3 * a[i];
            }
        }
    }
}

// Small-K (K=8) input projection accumulate (x @ Wih.T), reuses smem.
__device__ __forceinline__ void smallk_acc(
    float acc[4][8],
    const float* __restrict__ xA, int ldx,
    const float* __restrict__ W, // [2048][8]
    int gstride, int ubase, SmemT& sm)
{
    const int tid = threadIdx.x;
    float* xs = &sm.As[0][0];   // 64*8
    float* ws = &sm.Bs[0][0];   // 128*8
    __syncthreads();
    for (int i = tid; i < 64 * 8; i += 256)
        xs[i] = xA[(size_t)(i >> 3) * ldx + (i & 7)];
    for (int i = tid; i < 128 * 8; i += 256) {
        int jl = i >> 3;
        int jg = (jl >> 5) * gstride + ubase + (jl & 31);
        ws[i] = W[(size_t)jg * 8 + (i & 7)];
    }
    __syncthreads();
    const int u = tid & 31, rg = tid >> 5;
#pragma unroll
    for (int k = 0; k < 8; ++k) {
        float b0 = ws[(u) * 8 + k];
        float b1 = ws[(32 + u) * 8 + k];
        float b2 = ws[(64 + u) * 8 + k];
        float b3 = ws[(96 + u) * 8 + k];
#pragma unroll
        for (int i = 0; i < 8; ++i) {
            float a = xs[(rg * 8 + i) * 8 + k];
            acc[0][i] += b0 * a;
            acc[1][i] += b1 * a;
            acc[2][i] += b2 * a;
            acc[3][i] += b3 * a;
        }
    }
}

__device__ __forceinline__ float sigf(float v) { return 1.f / (1.f + expf(-v)); }

// Fused LSTM pointwise epilogue. All pointers pre-offset to the block row r0.
__device__ __forceinline__ void lstm_epilogue(
    float acc[4][8],
    const float* __restrict__ gbase,   // optional precomputed gates [row][2048] (incl bias)
    const float* __restrict__ bias,    // optional [2048]
    float* __restrict__ c,             // [row][512]
    float* __restrict__ hout,          // [row][512]
    float* __restrict__ yout, int ystride,  // optional
    int ubase)
{
    const int tid = threadIdx.x;
    const int u = tid & 31, rg = tid >> 5;
    const int ug = ubase + u;
    float b0 = 0.f, b1 = 0.f, b2 = 0.f, b3 = 0.f;
    if (bias) { b0 = bias[ug]; b1 = bias[512 + ug]; b2 = bias[1024 + ug]; b3 = bias[1536 + ug]; }
#pragma unroll
    for (int i = 0; i < 8; ++i) {
        int row = rg * 8 + i;
        float gi = acc[0][i] + b0;
        float gf = acc[1][i] + b1;
        float gg = acc[2][i] + b2;
        float go = acc[3][i] + b3;
        if (gbase) {
            const float* gb = gbase + (size_t)row * kG;
            gi += gb[ug]; gf += gb[512 + ug]; gg += gb[1024 + ug]; go += gb[1536 + ug];
        }
        gi = sigf(gi); gf = sigf(gf); gg = tanhf(gg); go = sigf(go);
        size_t idx = (size_t)row * kH + ug;
        float cv = gf * c[idx] + gi * gg;
        c[idx] = cv;
        float hv = go * tanhf(cv);
        hout[idx] = hv;
        if (yout) yout[(size_t)row * ystride + ug] = hv;
    }
}

// ---------------- kernels ----------------------------------------------------

__global__ void init_k()
{
    size_t i = (size_t)blockIdx.x * blockDim.x + threadIdx.x;
    size_t stride = (size_t)gridDim.x * blockDim.x;
    for (size_t j = i; j < (size_t)8 * kB * kH; j += stride) (&g_h[0][0])[j] = 0.f;
    for (size_t j = i; j < (size_t)4 * kB * kH; j += stride) (&g_c[0][0])[j] = 0.f;
}

// Encoder layer 0 step: both directions (blockIdx.z). Fuses x-projection (K=8).
__global__ __launch_bounds__(256) void enc_l0_step_k(
    const float* __restrict__ x, const float* __restrict__ Wih,
    const float* __restrict__ Whh, const float* __restrict__ bias,
    int t, int ping)
{
    __shared__ SmemT sm;
    int d = blockIdx.z;
    int s = d ? (kS - 1 - t) : t;
    int r0 = blockIdx.x * 64;
    int ubase = blockIdx.y * 32;
    float acc[4][8] = {};
    gemm_acc(acc, g_h[d * 2 + ping] + (size_t)r0 * kH, kH,
             Whh + (size_t)d * kG * kH, kH, kH, kH, ubase, sm);
    smallk_acc(acc, x + (size_t)r0 * (kS * kI) + (size_t)s * kI, kS * kI,
               Wih + (size_t)d * kG * kI, kH, ubase, sm);
    lstm_epilogue(acc, nullptr, bias + d * kG,
                  g_c[d] + (size_t)r0 * kH,
                  g_h[d * 2 + (ping ^ 1)] + (size_t)r0 * kH,
                  g_y0 + (size_t)s * kB * (2 * kH) + (size_t)r0 * (2 * kH) + (size_t)d * kH,
                  2 * kH, ubase);
}

// Batched L1 input projection: G1[d][s][b][:] = y0[s][b][:] @ Wih1[d].T + b1[d]
__global__ __launch_bounds__(256) void g1_gemm_k(
    const float* __restrict__ Wih1, const float* __restrict__ b1)
{
    __shared__ SmemT sm;
    int d = blockIdx.z;
    size_t m0 = (size_t)blockIdx.x * 64;
    int j0 = blockIdx.y * 128;
    float acc[4][8] = {};
    gemm_acc(acc, g_y0 + m0 * (2 * kH), 2 * kH,
             Wih1 + (size_t)d * kG * (2 * kH), 2 * kH, 2 * kH, 32, j0, sm);
    const int tid = threadIdx.x;
    const int u = tid & 31, rg = tid >> 5;
    float* C = g_G1 + (size_t)d * kS * kB * kG;
#pragma unroll
    for (int g = 0; g < 4; ++g) {
        int j = j0 + g * 32 + u;
        float bb = b1[d * kG + j];
#pragma unroll
        for (int i = 0; i < 8; ++i) {
            size_t m = m0 + rg * 8 + i;
            C[m * kG + j] = acc[g][i] + bb;
        }
    }
}

// Encoder layer 1 step: gates = G1[d][s] + h @ Whh1[d].T
__global__ __launch_bounds__(256) void enc_l1_step_k(
    const float* __restrict__ Whh1, int t, int ping)
{
    __shared__ SmemT sm;
    int d = blockIdx.z;
    int s = d ? (kS - 1 - t) : t;
    int r0 = blockIdx.x * 64;
    int ubase = blockIdx.y * 32;
    int run = 2 + d;
    float acc[4][8] = {};
    gemm_acc(acc, g_h[run * 2 + ping] + (size_t)r0 * kH, kH,
             Whh1 + (size_t)d * kG * kH, kH, kH, kH, ubase, sm);
    const float* gb = g_G1 + ((size_t)d * kS + s) * kB * kG + (size_t)r0 * kG;
    lstm_epilogue(acc, gb, nullptr,
                  g_c[2 + d] + (size_t)r0 * kH,
                  g_h[run * 2 + (ping ^ 1)] + (size_t)r0 * kH,
                  nullptr, 0, ubase);
}

// Sum fwd/bwd final states -> decoder init; grab last x timestep as dec input.
__global__ void combine_k(const float* __restrict__ x)
{
    int i = blockIdx.x * blockDim.x + threadIdx.x;
    if (i < kB * kH) {
        g_dh[0][i] = g_h[0][i] + g_h[2][i];
        g_dc[0][i] = g_c[0][i] + g_c[1][i];
        g_dh[2][i] = g_h[4][i] + g_h[6][i];
        g_dc[1][i] = g_c[2][i] + g_c[3][i];
    }
    if (i < kB * kI)
        g_din[i] = x[(size_t)(i >> 3) * (kS * kI) + (size_t)(kS - 1) * kI + (i & 7)];
}

__global__ __launch_bounds__(256) void dec_cell0_k(
    const float* __restrict__ Wih, const float* __restrict__ Whh,
    const float* __restrict__ bias, int ping)
{
    __shared__ SmemT sm;
    int r0 = blockIdx.x * 64;
    int ubase = blockIdx.y * 32;
    float acc[4][8] = {};
    gemm_acc(acc, g_dh[ping] + (size_t)r0 * kH, kH, Whh, kH, kH, kH, ubase, sm);
    smallk_acc(acc, g_din + (size_t)r0 * kI, kI, Wih, kH, ubase, sm);
    lstm_epilogue(acc, nullptr, bias,
                  g_dc[0] + (size_t)r0 * kH,
                  g_dh[ping ^ 1] + (size_t)r0 * kH, nullptr, 0, ubase);
}

__global__ __launch_bounds__(256) void dec_cell1_k(
    const float* __restrict__ Wih, const float* __restrict__ Whh,
    const float* __restrict__ bias, int p0new, int ping)
{
    __shared__ SmemT sm;
    int r0 = blockIdx.x * 64;
    int ubase = blockIdx.y * 32;
    float acc[4][8] = {};
    gemm_acc(acc, g_dh[2 + ping] + (size_t)r0 * kH, kH, Whh, kH, kH, kH, ubase, sm);
    gemm_acc(acc, g_dh[p0new] + (size_t)r0 * kH, kH, Wih, kH, kH, kH, ubase, sm);
    lstm_epilogue(acc, nullptr, bias,
                  g_dc[1] + (size_t)r0 * kH,
                  g_dh[2 + (ping ^ 1)] + (size_t)r0 * kH, nullptr, 0, ubase);
}

// z = relu(h1 @ fc1W.T + fc1b) ; tile 64 rows x 64 cols
__global__ __launch_bounds__(256) void fc1_k(
    const float* __restrict__ W, const float* __restrict__ b, int p1new)
{
    __shared__ float Hs[16][64];
    __shared__ float Ws[64][17];
    int r0 = blockIdx.x * 64;
    int j0 = blockIdx.y * 64;
    int tid = threadIdx.x;
    const float* h1 = g_dh[2 + p1new] + (size_t)r0 * kH;
    int j = tid & 63, rgrp = tid >> 6;
    float acc[16] = {};
    int lrow = tid >> 2, lk4 = (tid & 3) * 4;
    for (int k0 = 0; k0 < kH; k0 += 16) {
        __syncthreads();
        {
            float4 v = *reinterpret_cast<const float4*>(h1 + (size_t)lrow * kH + k0 + lk4);
            Hs[lk4 + 0][lrow] = v.x; Hs[lk4 + 1][lrow] = v.y;
            Hs[lk4 + 2][lrow] = v.z; Hs[lk4 + 3][lrow] = v.w;
        }
        {
            float4 v = *reinterpret_cast<const float4*>(W + (size_t)(j0 + lrow) * kH + k0 + lk4);
            Ws[lrow][lk4 + 0] = v.x; Ws[lrow][lk4 + 1] = v.y;
            Ws[lrow][lk4 + 2] = v.z; Ws[lrow][lk4 + 3] = v.w;
        }
        __syncthreads();
#pragma unroll
        for (int kk = 0; kk < 16; ++kk) {
            float w = Ws[j][kk];
#pragma unroll
            for (int r = 0; r < 16; ++r)
                acc[r] += Hs[kk][rgrp * 16 + r] * w;
        }
    }
    float bb = b[j0 + j];
#pragma unroll
    for (int r = 0; r < 16; ++r) {
        float v = acc[r] + bb;
        g_z[(size_t)(r0 + rgrp * 16 + r) * kF + j0 + j] = v > 0.f ? v : 0.f;
    }
}

// pred = z @ fc2W.T + fc2b ; write output column p; build next decoder input.
__global__ void fc2_k(
    const float* __restrict__ W2, const float* __restrict__ b2,
    const float* __restrict__ tf, float* __restrict__ out, int p)
{
    int w = threadIdx.x >> 5, lane = threadIdx.x & 31;
    int row = blockIdx.x * 8 + w;
    const float* z = g_z + (size_t)row * kF;
    float s = 0.f;
    for (int k = lane; k < kF; k += 32) s += z[k] * W2[k];
#pragma unroll
    for (int o = 16; o; o >>= 1) s += __shfl_xor_sync(0xffffffffu, s, o);
    if (lane == 0) {
        float pred = s + b2[0];
        out[row * kP + p] = pred;
        g_din[row * kI] = pred;  // next input feature 0
    }
    if (lane >= 1 && lane < 8)
        g_din[row * kI + lane] = tf[(size_t)row * (kP * kI) + (size_t)p * kI + lane];
}

// ---------------- host driver ------------------------------------------------
extern "C" void kernel_launch(void* const* d_in, const int* in_sizes, int n_in,
                              void* d_out, int out_size)
{
    (void)in_sizes; (void)n_in; (void)out_size;
    const float* x     = (const float*)d_in[0];
    const float* tf    = (const float*)d_in[1];
    const float* eWih0 = (const float*)d_in[2];
    const float* eWhh0 = (const float*)d_in[3];
    const float* eb0   = (const float*)d_in[4];
    const float* eWih1 = (const float*)d_in[5];
    const float* eWhh1 = (const float*)d_in[6];
    const float* eb1   = (const float*)d_in[7];
    const float* dWih0 = (const float*)d_in[8];
    const float* dWhh0 = (const float*)d_in[9];
    const float* db0   = (const float*)d_in[10];
    const float* dWih1 = (const float*)d_in[11];
    const float* dWhh1 = (const float*)d_in[12];
    const float* db1   = (const float*)d_in[13];
    const float* fc1W  = (const float*)d_in[14];
    const float* fc1b  = (const float*)d_in[15];
    const float* fc2W  = (const float*)d_in[16];
    const float* fc2b  = (const float*)d_in[17];
    float* out = (float*)d_out;

    init_k<<<512, 256>>>();

    // Encoder layer 0 (both directions per launch), fused x-projection.
    for (int t = 0; t < kS; ++t)
        enc_l0_step_k<<<dim3(8, 16, 2), 256>>>(x, eWih0, eWhh0, eb0, t, t & 1);

    // Batched layer-1 input projection (off the sequential chain).
    g1_gemm_k<<<dim3((kS * kB) / 64, kG / 128, 2), 256>>>(eWih1, eb1);

    // Encoder layer 1 recurrent chain (K=512 only).
    for (int t = 0; t < kS; ++t)
        enc_l1_step_k<<<dim3(8, 16, 2), 256>>>(eWhh1, t, t & 1);

    combine_k<<<1024, 256>>>(x);

    int p0 = 0, p1 = 0;
    for (int p = 0; p < kP; ++p) {
        dec_cell0_k<<<dim3(8, 16, 1), 256>>>(dWih0, dWhh0, db0, p0);
        dec_cell1_k<<<dim3(8, 16, 1), 256>>>(dWih1, dWhh1, db1, p0 ^ 1, p1);
        fc1_k<<<dim3(8, 4), 256>>>(fc1W, fc1b, p1 ^ 1);
        fc2_k<<<kB / 8, 256>>>(fc2W, fc2b, tf, out, p);
        p0 ^= 1; p1 ^= 1;
    }
}